// round 16
// baseline (speedup 1.0000x reference)
#include <cuda_runtime.h>
#include <cuda_fp16.h>
#include <stdint.h>
#include <math.h>

// ---------------- problem constants ----------------
constexpr int BB   = 4;
constexpr int CC   = 512;
constexpr int TT   = 16;
constexpr int HWc  = 1024;
constexpr int NN   = BB * HWc;      // 4096
constexpr int MM   = NN * TT;       // 65536
constexpr int NH   = 8;
constexpr int CH   = 64;
constexpr int GRP  = 32;
constexpr int CPG  = CC / GRP;      // 16
constexpr int C3   = 3 * CC;        // 1536
constexpr float EPSF = 1e-6f;

// ---------------- scratch (static device globals) ----------------
__device__ float g_mean[BB * GRP * HWc];
__device__ float g_rstd[BB * GRP * HWc];
__device__ __half g_nh[(size_t)MM * CC];
__device__ __half g_wqh[C3 * CC];
__device__ __half g_wph[CC * CC];
__device__ __half g_qkv[(size_t)MM * C3];
__device__ __half g_ah[(size_t)MM * CC];
__device__ __half g_pout[(size_t)MM * CC];
__device__ int g_dummy[1];

// ---------------- helpers ----------------
__device__ __forceinline__ uint32_t smem_u32(const void* p) {
    uint32_t a;
    asm("{ .reg .u64 t; cvta.to.shared.u64 t, %1; cvt.u32.u64 %0, t; }" : "=r"(a) : "l"(p));
    return a;
}
__device__ __forceinline__ void cpasync16(uint32_t dst, const void* src) {
    asm volatile("cp.async.cg.shared.global [%0], [%1], 16;" :: "r"(dst), "l"(src));
}
__device__ __forceinline__ void ldsm4(uint32_t* r, uint32_t a) {
    asm volatile("ldmatrix.sync.aligned.m8n8.x4.shared.b16 {%0,%1,%2,%3}, [%4];"
                 : "=r"(r[0]), "=r"(r[1]), "=r"(r[2]), "=r"(r[3]) : "r"(a));
}
__device__ __forceinline__ void ldsm4t(uint32_t* r, uint32_t a) {
    asm volatile("ldmatrix.sync.aligned.m8n8.x4.trans.shared.b16 {%0,%1,%2,%3}, [%4];"
                 : "=r"(r[0]), "=r"(r[1]), "=r"(r[2]), "=r"(r[3]) : "r"(a));
}
__device__ __forceinline__ void mma16816(float* d, const uint32_t* a, uint32_t b0, uint32_t b1) {
    asm volatile(
        "mma.sync.aligned.m16n8k16.row.col.f32.f16.f16.f32 "
        "{%0,%1,%2,%3},{%4,%5,%6,%7},{%8,%9},{%0,%1,%2,%3};"
        : "+f"(d[0]), "+f"(d[1]), "+f"(d[2]), "+f"(d[3])
        : "r"(a[0]), "r"(a[1]), "r"(a[2]), "r"(a[3]), "r"(b0), "r"(b1));
}

// ---------------- 0) dummy (shifts ncu profile slot) ----------------
__global__ void dummy_k() { if (threadIdx.x == 0) g_dummy[0] = 1; }

// ---------------- 1) fused: group-norm stats + weight convert ----------------
__global__ __launch_bounds__(1024) void gn_conv(const float* __restrict__ x,
                                                const float* __restrict__ wq,
                                                const float* __restrict__ wp) {
    int bx = blockIdx.x;
    if (bx < 128) {
        int b  = bx >> 5;
        int g  = bx & 31;
        int hw = threadIdx.x;
        float sum = 0.f, sq = 0.f;
        const float* base = x + ((size_t)b * CC + (size_t)g * CPG) * TT * HWc + hw;
        #pragma unroll 4
        for (int ct = 0; ct < CPG * TT; ct++) {
            float v = base[(size_t)ct * HWc];
            sum += v; sq += v * v;
        }
        float m   = sum * (1.0f / 256.0f);
        float var = sq  * (1.0f / 256.0f) - m * m;
        g_mean[(size_t)bx * HWc + hw] = m;
        g_rstd[(size_t)bx * HWc + hw] = rsqrtf(var + EPSF);
    } else {
        int i4 = (bx - 128) * 1024 + threadIdx.x;
        constexpr int NQ4 = C3 * CC / 4;
        const float4* src;
        __half* h;
        int idx;
        if (i4 < NQ4) { src = (const float4*)wq; h = g_wqh; idx = i4; }
        else          { src = (const float4*)wp; h = g_wph; idx = i4 - NQ4; }
        float4 v = src[idx];
        __half hh[4] = {__float2half(v.x), __float2half(v.y),
                        __float2half(v.z), __float2half(v.w)};
        uint2 uh;
        uh.x = *(uint32_t*)&hh[0]; uh.y = *(uint32_t*)&hh[2];
        *(uint2*)(h + idx * 4) = uh;
    }
}

// ---------------- 2) normalize + transpose to fp16 [M,512] ----------------
__global__ __launch_bounds__(256) void norm_tr(const float* __restrict__ x,
                                               const float* __restrict__ gamma,
                                               const float* __restrict__ beta) {
    __shared__ float tile[32][33];
    int bx  = blockIdx.x;
    int hwt = bx & 31;
    int ct  = (bx >> 5) & 15;
    int t   = (bx >> 9) & 15;
    int b   = bx >> 13;
    int tid = threadIdx.x;
    {
        int hw_l = tid & 31;
        int c_l0 = tid >> 5;
        int hw   = hwt * 32 + hw_l;
        #pragma unroll
        for (int p = 0; p < 4; p++) {
            int c_l = c_l0 + p * 8;
            int c   = ct * 32 + c_l;
            int g   = c >> 4;
            float v = x[(((size_t)b * CC + c) * TT + t) * HWc + hw];
            size_t si = ((size_t)(b * GRP + g)) * HWc + hw;
            v = (v - g_mean[si]) * g_rstd[si] * gamma[c] + beta[c];
            tile[c_l][hw_l] = v;
        }
    }
    __syncthreads();
    {
        int c2    = (tid & 15) * 2;
        int hw_l0 = tid >> 4;
        #pragma unroll
        for (int p = 0; p < 2; p++) {
            int hw_l = hw_l0 + p * 16;
            int hw   = hwt * 32 + hw_l;
            size_t m = ((size_t)(b * HWc + hw)) * TT + t;
            float v0 = tile[c2][hw_l];
            float v1 = tile[c2 + 1][hw_l];
            size_t idx = m * CC + ct * 32 + c2;
            *(__half2*)(g_nh + idx) = __halves2half2(__float2half(v0), __float2half(v1));
        }
    }
}

// ---------------- HMMA GEMM: CTA 128x64, warp 32x32, 3 CTAs/SM target ----------------
constexpr int PITCH   = 80;
constexpr int A_TILE  = 128 * PITCH;        // 10240
constexpr int B_TILE  = 64 * PITCH;         // 5120
constexpr int STAGE_B = A_TILE + B_TILE;    // 15360
constexpr int GEMM_SMEM = 4 * STAGE_B;      // 61440

__global__ __launch_bounds__(256, 3) void hmma_gemm(const __half* __restrict__ A,
                                                    const __half* __restrict__ B,
                                                    const float* __restrict__ bias,
                                                    __half* __restrict__ Cout, int ldc) {
    extern __shared__ char smem[];
    uint32_t sb = smem_u32(smem);
    int tid = threadIdx.x;
    int n0 = blockIdx.x * 64;
    int m0 = blockIdx.y * 128;

    // loader: 768 chunks of 16B per stage (A: 512, B: 256); 3 per thread
    const int4* lp[3];
    uint32_t ld[3];
    #pragma unroll
    for (int it = 0; it < 3; it++) {
        int id  = it * 256 + tid;
        int isA = id < 512;
        int rid = isA ? id : id - 512;
        int row = rid >> 2;
        int col = rid & 3;
        lp[it] = (isA ? (const int4*)A + (size_t)(m0 + row) * 64
                      : (const int4*)B + (size_t)(n0 + row) * 64) + col;
        ld[it] = sb + (isA ? 0 : A_TILE) + row * PITCH + col * 16;
    }
    auto issue = [&](int kk, int stage) {
        int ko = kk * 4;
        #pragma unroll
        for (int it = 0; it < 3; it++)
            cpasync16(ld[it] + stage * STAGE_B, lp[it] + ko);
        asm volatile("cp.async.commit_group;");
    };

    float acc[2][4][4];
    #pragma unroll
    for (int a = 0; a < 2; a++)
        #pragma unroll
        for (int b = 0; b < 4; b++)
            #pragma unroll
            for (int cc = 0; cc < 4; cc++) acc[a][b][cc] = 0.f;

    int wid = tid >> 5, lane = tid & 31;
    int mw  = (wid >> 1) * 32;     // 4 m-groups of 32
    int nwv = (wid & 1) * 32;      // 2 n-groups of 32
    int lrow = lane & 15;
    int lk   = (lane >> 4) * 16;
    uint32_t adab = (mw + lrow) * PITCH + lk;
    uint32_t bdab = A_TILE + (nwv + lrow) * PITCH + lk;

    uint32_t amA[2][4], bmA[2][4];
    uint32_t amB[2][4], bmB[2][4];

    auto load_frags = [&](uint32_t am[2][4], uint32_t bm[2][4], uint32_t sa, int j) {
        #pragma unroll
        for (int mt = 0; mt < 2; mt++)
            ldsm4(am[mt], sa + adab + mt * (16 * PITCH) + j * 32);
        #pragma unroll
        for (int bt = 0; bt < 2; bt++)
            ldsm4(bm[bt], sa + bdab + bt * (16 * PITCH) + j * 32);
    };
    auto mma_all = [&](uint32_t am[2][4], uint32_t bm[2][4]) {
        #pragma unroll
        for (int mt = 0; mt < 2; mt++)
            #pragma unroll
            for (int nt = 0; nt < 4; nt++) {
                int bt = nt >> 1, s = nt & 1;
                mma16816(acc[mt][nt], am[mt], bm[bt][s], bm[bt][2 + s]);
            }
    };

    issue(0, 0);
    issue(1, 1);
    issue(2, 2);
    asm volatile("cp.async.wait_group 2;");
    __syncthreads();
    load_frags(amA, bmA, sb, 0);

    #pragma unroll 1
    for (int ks = 0; ks < 16; ks++) {
        if (ks < 14) asm volatile("cp.async.wait_group 1;");
        else         asm volatile("cp.async.wait_group 0;");
        __syncthreads();
        if (ks + 3 < 16) issue(ks + 3, (ks + 3) & 3);

        uint32_t sa  = sb + (ks & 3) * STAGE_B;
        uint32_t san = sb + ((ks + 1) & 3) * STAGE_B;

        load_frags(amB, bmB, sa, 1);
        mma_all(amA, bmA);
        if (ks < 15) load_frags(amA, bmA, san, 0);
        mma_all(amB, bmB);
    }

    int row_in = lane >> 2;
    int colq   = (lane & 3) * 2;
    #pragma unroll
    for (int mt = 0; mt < 2; mt++) {
        int gr = m0 + mw + mt * 16 + row_in;
        #pragma unroll
        for (int nt = 0; nt < 4; nt++) {
            int gc = n0 + nwv + nt * 8 + colq;
            float b0 = bias[gc], b1 = bias[gc + 1];
            *(__half2*)(Cout + (size_t)gr * ldc + gc) =
                __halves2half2(__float2half(acc[mt][nt][0] + b0),
                               __float2half(acc[mt][nt][1] + b1));
            *(__half2*)(Cout + (size_t)(gr + 8) * ldc + gc) =
                __halves2half2(__float2half(acc[mt][nt][2] + b0),
                               __float2half(acc[mt][nt][3] + b1));
        }
    }
}

// ---------------- 4) attention via HMMA (R13, unchanged) ----------------
constexpr int QPH  = 520;
constexpr int RPH  = 72;
constexpr int WSP  = 17;
constexpr int WRP  = 33;
constexpr int WP   = 24;
constexpr int W2P  = 40;
constexpr int OFFB_Q  = 0;
constexpr int OFFB_K  = OFFB_Q  + 16 * QPH * 2;
constexpr int OFFB_V  = OFFB_K  + 16 * QPH * 2;
constexpr int OFFB_RK = OFFB_V  + 16 * QPH * 2;
constexpr int OFFB_RV = OFFB_RK + 32 * RPH * 2;
constexpr int OFFB_WS = OFFB_RV + 32 * RPH * 2;
constexpr int OFFB_WR = OFFB_WS + 8 * 16 * WSP * 4;
constexpr int OFFB_W  = OFFB_WR + 8 * 16 * WRP * 4;
constexpr int OFFB_W2 = OFFB_W  + 8 * 16 * WP * 2;
constexpr int ATTN_SMEM = OFFB_W2 + 8 * 16 * W2P * 2;

__global__ __launch_bounds__(256, 2) void attn(const float* __restrict__ rp_k,
                                               const float* __restrict__ rp_v) {
    extern __shared__ char smc[];
    uint32_t sb = smem_u32(smc);
    __half* rkh = (__half*)(smc + OFFB_RK);
    __half* rvh = (__half*)(smc + OFFB_RV);
    float*  wsf = (float*)(smc + OFFB_WS);
    float*  wrf = (float*)(smc + OFFB_WR);
    __half* wh  = (__half*)(smc + OFFB_W);
    __half* w2h = (__half*)(smc + OFFB_W2);

    int n   = blockIdx.x;
    int tid = threadIdx.x;
    int wid = tid >> 5, lane = tid & 31;

    const uint4* gq = reinterpret_cast<const uint4*>(g_qkv);
    #pragma unroll
    for (int it = 0; it < 12; it++) {
        int idx = it * 256 + tid;
        int t   = idx / 192;
        int rem = idx - t * 192;
        int which = rem >> 6;
        int c8    = rem & 63;
        uint4 raw = gq[(size_t)(n * TT + t) * 192 + rem];
        *(uint4*)(smc + OFFB_Q + which * (16 * QPH * 2) + (t * QPH + c8 * 8) * 2) = raw;
    }
    const float4* grk = reinterpret_cast<const float4*>(rp_k);
    const float4* grv = reinterpret_cast<const float4*>(rp_v);
    for (int idx = tid; idx < 992; idx += 256) {
        int hsel = idx >= 496;
        int r = idx - hsel * 496;
        int row = r >> 4, c4 = r & 15;
        float4 val = (hsel ? grv : grk)[(49 + row) * 16 + c4];
        __half h0 = __float2half(val.x), h1 = __float2half(val.y);
        __half h2 = __float2half(val.z), h3 = __float2half(val.w);
        uint2 u;
        u.x = ((uint32_t)*(uint16_t*)&h1 << 16) | *(uint16_t*)&h0;
        u.y = ((uint32_t)*(uint16_t*)&h3 << 16) | *(uint16_t*)&h2;
        *(uint2*)((hsel ? rvh : rkh) + row * RPH + c4 * 4) = u;
    }
    if (tid < 18) {
        int a = tid / 9, q4 = tid % 9;
        *(uint4*)((a ? rvh : rkh) + 31 * RPH + q4 * 8) = make_uint4(0, 0, 0, 0);
    }
    __syncthreads();

    {
        int h = wid;
        int lrow = lane & 15;
        int lk8  = (lane >> 4) * 8;
        float accS[2][4], accR[4][4];
        #pragma unroll
        for (int i = 0; i < 2; i++)
            #pragma unroll
            for (int j = 0; j < 4; j++) accS[i][j] = 0.f;
        #pragma unroll
        for (int i = 0; i < 4; i++)
            #pragma unroll
            for (int j = 0; j < 4; j++) accR[i][j] = 0.f;

        #pragma unroll
        for (int kc = 0; kc < 4; kc++) {
            int coff = h * 64 + kc * 16 + lk8;
            uint32_t aq[4], bk[4], br0[4], br1[4];
            ldsm4(aq, sb + OFFB_Q + (lrow * QPH + coff) * 2);
            ldsm4(bk, sb + OFFB_K + (lrow * QPH + coff) * 2);
            ldsm4(br0, sb + OFFB_RK + (lrow * RPH + kc * 16 + lk8) * 2);
            ldsm4(br1, sb + OFFB_RK + ((lrow + 16) * RPH + kc * 16 + lk8) * 2);
            mma16816(accS[0], aq, bk[0], bk[2]);
            mma16816(accS[1], aq, bk[1], bk[3]);
            mma16816(accR[0], aq, br0[0], br0[2]);
            mma16816(accR[1], aq, br0[1], br0[3]);
            mma16816(accR[2], aq, br1[0], br1[2]);
            mma16816(accR[3], aq, br1[1], br1[3]);
        }
        int dr = lane >> 2;
        int dc = (lane & 3) * 2;
        float* wsb = wsf + h * 16 * WSP;
        float* wrb = wrf + h * 16 * WRP;
        #pragma unroll
        for (int s = 0; s < 2; s++) {
            int col = s * 8 + dc;
            wsb[dr * WSP + col]           = accS[s][0];
            wsb[dr * WSP + col + 1]       = accS[s][1];
            wsb[(dr + 8) * WSP + col]     = accS[s][2];
            wsb[(dr + 8) * WSP + col + 1] = accS[s][3];
        }
        #pragma unroll
        for (int s = 0; s < 4; s++) {
            int col = s * 8 + dc;
            wrb[dr * WRP + col]           = accR[s][0];
            wrb[dr * WRP + col + 1]       = accR[s][1];
            wrb[(dr + 8) * WRP + col]     = accR[s][2];
            wrb[(dr + 8) * WRP + col + 1] = accR[s][3];
        }
    }
    __syncthreads();

    if (tid < 128) {
        int h = tid >> 4, i = tid & 15;
        const float* wsb = wsf + h * 16 * WSP + i * WSP;
        const float* wrb = wrf + h * 16 * WRP;
        float s[16];
        float mx = -1e30f;
        #pragma unroll
        for (int j = 0; j < 16; j++) {
            s[j] = 0.125f * wsb[j] + 0.35355339059327373f * wrb[j * WRP + (i - j + 15)];
            mx = fmaxf(mx, s[j]);
        }
        float sum = 0.f;
        #pragma unroll
        for (int j = 0; j < 16; j++) { s[j] = __expf(s[j] - mx); sum += s[j]; }
        float inv = 1.f / sum;
        __half* w2b = w2h + (h * 16 + i) * W2P;
        #pragma unroll
        for (int q4 = 0; q4 < 4; q4++) *(uint4*)(w2b + q4 * 8) = make_uint4(0, 0, 0, 0);
        __half* wb = wh + (h * 16 + i) * WP;
        #pragma unroll
        for (int j = 0; j < 16; j++) {
            float w = s[j] * inv;
            __half hw_ = __float2half(w);
            wb[j] = hw_;
            w2b[j - i + 15] = hw_;
        }
    }
    __syncthreads();

    {
        int h = wid;
        int lrow = lane & 15;
        int lk8  = (lane >> 4) * 8;
        float accO[8][4];
        #pragma unroll
        for (int i = 0; i < 8; i++)
            #pragma unroll
            for (int j = 0; j < 4; j++) accO[i][j] = 0.f;

        uint32_t aw[4], aw2a[4], aw2b[4];
        ldsm4(aw,   sb + OFFB_W  + (h * 16 * WP  + lrow * WP  + lk8) * 2);
        ldsm4(aw2a, sb + OFFB_W2 + (h * 16 * W2P + lrow * W2P + lk8) * 2);
        ldsm4(aw2b, sb + OFFB_W2 + (h * 16 * W2P + lrow * W2P + 16 + lk8) * 2);

        #pragma unroll
        for (int nc = 0; nc < 4; nc++) {
            int coff = h * 64 + nc * 16 + lk8;
            uint32_t bv[4], brv0[4], brv1[4];
            ldsm4t(bv,   sb + OFFB_V  + (lrow * QPH + coff) * 2);
            ldsm4t(brv0, sb + OFFB_RV + (lrow * RPH + nc * 16 + lk8) * 2);
            ldsm4t(brv1, sb + OFFB_RV + ((lrow + 16) * RPH + nc * 16 + lk8) * 2);
            mma16816(accO[nc * 2 + 0], aw, bv[0], bv[1]);
            mma16816(accO[nc * 2 + 1], aw, bv[2], bv[3]);
            mma16816(accO[nc * 2 + 0], aw2a, brv0[0], brv0[1]);
            mma16816(accO[nc * 2 + 1], aw2a, brv0[2], brv0[3]);
            mma16816(accO[nc * 2 + 0], aw2b, brv1[0], brv1[1]);
            mma16816(accO[nc * 2 + 1], aw2b, brv1[2], brv1[3]);
        }

        int dr = lane >> 2;
        int dc = (lane & 3) * 2;
        #pragma unroll
        for (int nc8 = 0; nc8 < 8; nc8++) {
            int col = h * 64 + nc8 * 8 + dc;
            size_t i0 = ((size_t)(n * TT + dr)) * CC + col;
            size_t i1 = ((size_t)(n * TT + dr + 8)) * CC + col;
            *(__half2*)(g_ah + i0) =
                __halves2half2(__float2half(accO[nc8][0]), __float2half(accO[nc8][1]));
            *(__half2*)(g_ah + i1) =
                __halves2half2(__float2half(accO[nc8][2]), __float2half(accO[nc8][3]));
        }
    }
}

// ---------------- 6) transpose back + residual (fp16 pout) ----------------
__global__ __launch_bounds__(256) void resid_tr(const float* __restrict__ x,
                                                float* __restrict__ out) {
    __shared__ float tile[32][33];
    int bx  = blockIdx.x;
    int hwt = bx & 31;
    int ct  = (bx >> 5) & 15;
    int t   = (bx >> 9) & 15;
    int b   = bx >> 13;
    int tid = threadIdx.x;
    {
        int c2    = (tid & 15) * 2;
        int hw_l0 = tid >> 4;
        #pragma unroll
        for (int p = 0; p < 2; p++) {
            int hw_l = hw_l0 + p * 16;
            int hw   = hwt * 32 + hw_l;
            size_t m = ((size_t)(b * HWc + hw)) * TT + t;
            __half2 hv = *(const __half2*)(g_pout + m * CC + ct * 32 + c2);
            float2 f = __half22float2(hv);
            tile[hw_l][c2]     = f.x;
            tile[hw_l][c2 + 1] = f.y;
        }
    }
    __syncthreads();
    {
        int hw_l = tid & 31;
        int c_l0 = tid >> 5;
        int hw   = hwt * 32 + hw_l;
        #pragma unroll
        for (int p = 0; p < 4; p++) {
            int c_l = c_l0 + p * 8;
            int c   = ct * 32 + c_l;
            size_t idx = (((size_t)b * CC + c) * TT + t) * HWc + hw;
            out[idx] = x[idx] + tile[hw_l][c_l];
        }
    }
}

// ---------------- host launch ----------------
extern "C" void kernel_launch(void* const* d_in, const int* in_sizes, int n_in,
                              void* d_out, int out_size) {
    const float* x      = (const float*)d_in[0];
    const float* gamma  = (const float*)d_in[1];
    const float* beta   = (const float*)d_in[2];
    const float* w_qkv  = (const float*)d_in[3];
    const float* b_qkv  = (const float*)d_in[4];
    const float* rp_k   = (const float*)d_in[5];
    const float* rp_v   = (const float*)d_in[6];
    const float* w_proj = (const float*)d_in[7];
    const float* b_proj = (const float*)d_in[8];
    float* out = (float*)d_out;

    cudaFuncSetAttribute(hmma_gemm, cudaFuncAttributeMaxDynamicSharedMemorySize, GEMM_SMEM);
    cudaFuncSetAttribute(attn, cudaFuncAttributeMaxDynamicSharedMemorySize, ATTN_SMEM);

    __half *wqh, *wph, *nh, *ah, *qkv, *pout;
    cudaGetSymbolAddress((void**)&wqh, g_wqh);
    cudaGetSymbolAddress((void**)&wph, g_wph);
    cudaGetSymbolAddress((void**)&nh, g_nh);
    cudaGetSymbolAddress((void**)&ah, g_ah);
    cudaGetSymbolAddress((void**)&qkv, g_qkv);
    cudaGetSymbolAddress((void**)&pout, g_pout);

    // dummy keeps qkv GEMM in ncu slot #4 (verify occupancy hypothesis)
    dummy_k<<<1, 32>>>();
    gn_conv<<<384, 1024>>>(x, w_qkv, w_proj);
    norm_tr<<<BB * TT * (CC / 32) * (HWc / 32), 256>>>(x, gamma, beta);
    hmma_gemm<<<dim3(C3 / 64, MM / 128), 256, GEMM_SMEM>>>(nh, wqh, b_qkv, qkv, C3);
    attn<<<NN, 256, ATTN_SMEM>>>(rp_k, rp_v);
    hmma_gemm<<<dim3(CC / 64, MM / 128), 256, GEMM_SMEM>>>(ah, wph, b_proj, pout, CC);
    resid_tr<<<BB * TT * (CC / 32) * (HWc / 32), 256>>>(x, out);
}

// round 17
// speedup vs baseline: 1.1357x; 1.1357x over previous
#include <cuda_runtime.h>
#include <cuda_fp16.h>
#include <stdint.h>
#include <math.h>

// ---------------- problem constants ----------------
constexpr int BB   = 4;
constexpr int CC   = 512;
constexpr int TT   = 16;
constexpr int HWc  = 1024;
constexpr int NN   = BB * HWc;      // 4096
constexpr int MM   = NN * TT;       // 65536
constexpr int NH   = 8;
constexpr int CH   = 64;
constexpr int GRP  = 32;
constexpr int CPG  = CC / GRP;      // 16
constexpr int C3   = 3 * CC;        // 1536
constexpr float EPSF = 1e-6f;

// ---------------- scratch (static device globals) ----------------
__device__ float g_mean[BB * GRP * HWc];
__device__ float g_rstd[BB * GRP * HWc];
__device__ __half g_nh[(size_t)MM * CC];
__device__ __half g_wqh[C3 * CC];
__device__ __half g_wph[CC * CC];
__device__ __half g_qkv[(size_t)MM * C3];
__device__ __half g_ah[(size_t)MM * CC];
__device__ __half g_pout[(size_t)MM * CC];

// ---------------- helpers ----------------
__device__ __forceinline__ uint32_t smem_u32(const void* p) {
    uint32_t a;
    asm("{ .reg .u64 t; cvta.to.shared.u64 t, %1; cvt.u32.u64 %0, t; }" : "=r"(a) : "l"(p));
    return a;
}
__device__ __forceinline__ void cpasync16(uint32_t dst, const void* src) {
    asm volatile("cp.async.cg.shared.global [%0], [%1], 16;" :: "r"(dst), "l"(src));
}
__device__ __forceinline__ void ldsm4(uint32_t* r, uint32_t a) {
    asm volatile("ldmatrix.sync.aligned.m8n8.x4.shared.b16 {%0,%1,%2,%3}, [%4];"
                 : "=r"(r[0]), "=r"(r[1]), "=r"(r[2]), "=r"(r[3]) : "r"(a));
}
__device__ __forceinline__ void ldsm4t(uint32_t* r, uint32_t a) {
    asm volatile("ldmatrix.sync.aligned.m8n8.x4.trans.shared.b16 {%0,%1,%2,%3}, [%4];"
                 : "=r"(r[0]), "=r"(r[1]), "=r"(r[2]), "=r"(r[3]) : "r"(a));
}
__device__ __forceinline__ void mma16816(float* d, const uint32_t* a, uint32_t b0, uint32_t b1) {
    asm volatile(
        "mma.sync.aligned.m16n8k16.row.col.f32.f16.f16.f32 "
        "{%0,%1,%2,%3},{%4,%5,%6,%7},{%8,%9},{%0,%1,%2,%3};"
        : "+f"(d[0]), "+f"(d[1]), "+f"(d[2]), "+f"(d[3])
        : "r"(a[0]), "r"(a[1]), "r"(a[2]), "r"(a[3]), "r"(b0), "r"(b1));
}

// ---------------- 1) fused: group-norm stats + weight convert ----------------
__global__ __launch_bounds__(1024) void gn_conv(const float* __restrict__ x,
                                                const float* __restrict__ wq,
                                                const float* __restrict__ wp) {
    int bx = blockIdx.x;
    if (bx < 128) {
        int b  = bx >> 5;
        int g  = bx & 31;
        int hw = threadIdx.x;
        float sum = 0.f, sq = 0.f;
        const float* base = x + ((size_t)b * CC + (size_t)g * CPG) * TT * HWc + hw;
        #pragma unroll 4
        for (int ct = 0; ct < CPG * TT; ct++) {
            float v = base[(size_t)ct * HWc];
            sum += v; sq += v * v;
        }
        float m   = sum * (1.0f / 256.0f);
        float var = sq  * (1.0f / 256.0f) - m * m;
        g_mean[(size_t)bx * HWc + hw] = m;
        g_rstd[(size_t)bx * HWc + hw] = rsqrtf(var + EPSF);
    } else {
        int i4 = (bx - 128) * 1024 + threadIdx.x;
        constexpr int NQ4 = C3 * CC / 4;
        const float4* src;
        __half* h;
        int idx;
        if (i4 < NQ4) { src = (const float4*)wq; h = g_wqh; idx = i4; }
        else          { src = (const float4*)wp; h = g_wph; idx = i4 - NQ4; }
        float4 v = src[idx];
        __half hh[4] = {__float2half(v.x), __float2half(v.y),
                        __float2half(v.z), __float2half(v.w)};
        uint2 uh;
        uh.x = *(uint32_t*)&hh[0]; uh.y = *(uint32_t*)&hh[2];
        *(uint2*)(h + idx * 4) = uh;
    }
}

// ---------------- 2) normalize + transpose to fp16 [M,512] ----------------
__global__ __launch_bounds__(256) void norm_tr(const float* __restrict__ x,
                                               const float* __restrict__ gamma,
                                               const float* __restrict__ beta) {
    __shared__ float tile[32][33];
    int bx  = blockIdx.x;
    int hwt = bx & 31;
    int ct  = (bx >> 5) & 15;
    int t   = (bx >> 9) & 15;
    int b   = bx >> 13;
    int tid = threadIdx.x;
    {
        int hw_l = tid & 31;
        int c_l0 = tid >> 5;
        int hw   = hwt * 32 + hw_l;
        #pragma unroll
        for (int p = 0; p < 4; p++) {
            int c_l = c_l0 + p * 8;
            int c   = ct * 32 + c_l;
            int g   = c >> 4;
            float v = x[(((size_t)b * CC + c) * TT + t) * HWc + hw];
            size_t si = ((size_t)(b * GRP + g)) * HWc + hw;
            v = (v - g_mean[si]) * g_rstd[si] * gamma[c] + beta[c];
            tile[c_l][hw_l] = v;
        }
    }
    __syncthreads();
    {
        int c2    = (tid & 15) * 2;
        int hw_l0 = tid >> 4;
        #pragma unroll
        for (int p = 0; p < 2; p++) {
            int hw_l = hw_l0 + p * 16;
            int hw   = hwt * 32 + hw_l;
            size_t m = ((size_t)(b * HWc + hw)) * TT + t;
            float v0 = tile[c2][hw_l];
            float v1 = tile[c2 + 1][hw_l];
            size_t idx = m * CC + ct * 32 + c2;
            *(__half2*)(g_nh + idx) = __halves2half2(__float2half(v0), __float2half(v1));
        }
    }
}

// ---------------- HMMA GEMM (R13-proven config, frozen) ----------------
constexpr int PITCH   = 80;
constexpr int TILE_B  = 128 * PITCH;   // 10240
constexpr int STAGE_B = 2 * TILE_B;    // 20480
constexpr int GEMM_SMEM = 4 * STAGE_B; // 81920

__global__ __launch_bounds__(256, 2) void hmma_gemm(const __half* __restrict__ A,
                                                    const __half* __restrict__ B,
                                                    const float* __restrict__ bias,
                                                    __half* __restrict__ Cout, int ldc) {
    extern __shared__ char smem[];
    uint32_t sb = smem_u32(smem);
    int tid = threadIdx.x;
    int n0 = blockIdx.x * 128;
    int m0 = blockIdx.y * 128;

    int r = tid >> 2;
    int c = tid & 3;
    const int4* pA = (const int4*)A + (size_t)(m0 + r) * 64 + c;
    const int4* pB = (const int4*)B + (size_t)(n0 + r) * 64 + c;
    uint32_t d0 = sb + r * PITCH + c * 16;
    constexpr int RSTEP = 64 * 64;
    constexpr int DSTEP = 64 * PITCH;

    auto issue = [&](int kk, int stage) {
        uint32_t dst = d0 + stage * STAGE_B;
        int ko = kk * 4;
        cpasync16(dst,                   pA + ko);
        cpasync16(dst + DSTEP,           pA + ko + RSTEP);
        cpasync16(dst + TILE_B,          pB + ko);
        cpasync16(dst + TILE_B + DSTEP,  pB + ko + RSTEP);
        asm volatile("cp.async.commit_group;");
    };

    float acc[4][4][4];
    #pragma unroll
    for (int a = 0; a < 4; a++)
        #pragma unroll
        for (int b = 0; b < 4; b++)
            #pragma unroll
            for (int cc = 0; cc < 4; cc++) acc[a][b][cc] = 0.f;

    int wid = tid >> 5, lane = tid & 31;
    int mw  = (wid >> 2) * 64;
    int nwv = (wid & 3) * 32;
    int lrow = lane & 15;
    int lk   = (lane >> 4) * 16;
    uint32_t adab = (mw + lrow) * PITCH + lk;
    uint32_t bdab = TILE_B + (nwv + lrow) * PITCH + lk;

    uint32_t amA[4][4], bmA[2][4];
    uint32_t amB[4][4], bmB[2][4];

    auto load_frags = [&](uint32_t am[4][4], uint32_t bm[2][4], uint32_t sa, int j) {
        #pragma unroll
        for (int mt = 0; mt < 4; mt++)
            ldsm4(am[mt], sa + adab + mt * (16 * PITCH) + j * 32);
        #pragma unroll
        for (int bt = 0; bt < 2; bt++)
            ldsm4(bm[bt], sa + bdab + bt * (16 * PITCH) + j * 32);
    };
    auto mma_all = [&](uint32_t am[4][4], uint32_t bm[2][4]) {
        #pragma unroll
        for (int mt = 0; mt < 4; mt++)
            #pragma unroll
            for (int nt = 0; nt < 4; nt++) {
                int bt = nt >> 1, s = nt & 1;
                mma16816(acc[mt][nt], am[mt], bm[bt][s], bm[bt][2 + s]);
            }
    };

    issue(0, 0);
    issue(1, 1);
    issue(2, 2);
    asm volatile("cp.async.wait_group 2;");
    __syncthreads();
    load_frags(amA, bmA, sb, 0);

    #pragma unroll 1
    for (int ks = 0; ks < 16; ks++) {
        if (ks < 14) asm volatile("cp.async.wait_group 1;");
        else         asm volatile("cp.async.wait_group 0;");
        __syncthreads();
        if (ks + 3 < 16) issue(ks + 3, (ks + 3) & 3);

        uint32_t sa  = sb + (ks & 3) * STAGE_B;
        uint32_t san = sb + ((ks + 1) & 3) * STAGE_B;

        load_frags(amB, bmB, sa, 1);
        mma_all(amA, bmA);
        if (ks < 15) load_frags(amA, bmA, san, 0);
        mma_all(amB, bmB);
    }

    int row_in = lane >> 2;
    int colq   = (lane & 3) * 2;
    #pragma unroll
    for (int mt = 0; mt < 4; mt++) {
        int gr = m0 + mw + mt * 16 + row_in;
        #pragma unroll
        for (int nt = 0; nt < 4; nt++) {
            int gc = n0 + nwv + nt * 8 + colq;
            float b0 = bias[gc], b1 = bias[gc + 1];
            *(__half2*)(Cout + (size_t)gr * ldc + gc) =
                __halves2half2(__float2half(acc[mt][nt][0] + b0),
                               __float2half(acc[mt][nt][1] + b1));
            *(__half2*)(Cout + (size_t)(gr + 8) * ldc + gc) =
                __halves2half2(__float2half(acc[mt][nt][2] + b0),
                               __float2half(acc[mt][nt][3] + b1));
        }
    }
}

// ---------------- 4) attention via HMMA, cp.async load phase ----------------
constexpr int QPH  = 520;
constexpr int RPH  = 72;
constexpr int WSP  = 17;
constexpr int WRP  = 33;
constexpr int WP   = 24;
constexpr int W2P  = 40;
constexpr int OFFB_Q  = 0;
constexpr int OFFB_K  = OFFB_Q  + 16 * QPH * 2;
constexpr int OFFB_V  = OFFB_K  + 16 * QPH * 2;
constexpr int OFFB_RK = OFFB_V  + 16 * QPH * 2;
constexpr int OFFB_RV = OFFB_RK + 32 * RPH * 2;
constexpr int OFFB_WS = OFFB_RV + 32 * RPH * 2;
constexpr int OFFB_WR = OFFB_WS + 8 * 16 * WSP * 4;
constexpr int OFFB_W  = OFFB_WR + 8 * 16 * WRP * 4;
constexpr int OFFB_W2 = OFFB_W  + 8 * 16 * WP * 2;
constexpr int ATTN_SMEM = OFFB_W2 + 8 * 16 * W2P * 2;

__global__ __launch_bounds__(256, 2) void attn(const float* __restrict__ rp_k,
                                               const float* __restrict__ rp_v) {
    extern __shared__ char smc[];
    uint32_t sb = smem_u32(smc);
    __half* rkh = (__half*)(smc + OFFB_RK);
    __half* rvh = (__half*)(smc + OFFB_RV);
    float*  wsf = (float*)(smc + OFFB_WS);
    float*  wrf = (float*)(smc + OFFB_WR);
    __half* wh  = (__half*)(smc + OFFB_W);
    __half* w2h = (__half*)(smc + OFFB_W2);

    int n   = blockIdx.x;
    int tid = threadIdx.x;
    int wid = tid >> 5, lane = tid & 31;

    // ---- qkv loads via cp.async (overlap with rp conversion below) ----
    const uint4* gq = reinterpret_cast<const uint4*>(g_qkv);
    #pragma unroll
    for (int it = 0; it < 12; it++) {
        int idx = it * 256 + tid;
        int t   = idx / 192;
        int rem = idx - t * 192;
        int which = rem >> 6;
        int c8    = rem & 63;
        uint32_t dst = sb + OFFB_Q + which * (16 * QPH * 2) + (t * QPH + c8 * 8) * 2;
        cpasync16(dst, gq + (size_t)(n * TT + t) * 192 + rem);
    }
    asm volatile("cp.async.commit_group;");

    // rp rows 0..30 (dist 49..79), fp16; row 31 zero — overlaps the cp.async
    const float4* grk = reinterpret_cast<const float4*>(rp_k);
    const float4* grv = reinterpret_cast<const float4*>(rp_v);
    for (int idx = tid; idx < 992; idx += 256) {
        int hsel = idx >= 496;
        int r = idx - hsel * 496;
        int row = r >> 4, c4 = r & 15;
        float4 val = (hsel ? grv : grk)[(49 + row) * 16 + c4];
        __half h0 = __float2half(val.x), h1 = __float2half(val.y);
        __half h2 = __float2half(val.z), h3 = __float2half(val.w);
        uint2 u;
        u.x = ((uint32_t)*(uint16_t*)&h1 << 16) | *(uint16_t*)&h0;
        u.y = ((uint32_t)*(uint16_t*)&h3 << 16) | *(uint16_t*)&h2;
        *(uint2*)((hsel ? rvh : rkh) + row * RPH + c4 * 4) = u;
    }
    if (tid < 18) {
        int a = tid / 9, q4 = tid % 9;
        *(uint4*)((a ? rvh : rkh) + 31 * RPH + q4 * 8) = make_uint4(0, 0, 0, 0);
    }
    asm volatile("cp.async.wait_group 0;");
    __syncthreads();

    // ---- score phase: Sc = Q*K^T, R = Q*RK^T ----
    {
        int h = wid;
        int lrow = lane & 15;
        int lk8  = (lane >> 4) * 8;
        float accS[2][4], accR[4][4];
        #pragma unroll
        for (int i = 0; i < 2; i++)
            #pragma unroll
            for (int j = 0; j < 4; j++) accS[i][j] = 0.f;
        #pragma unroll
        for (int i = 0; i < 4; i++)
            #pragma unroll
            for (int j = 0; j < 4; j++) accR[i][j] = 0.f;

        #pragma unroll
        for (int kc = 0; kc < 4; kc++) {
            int coff = h * 64 + kc * 16 + lk8;
            uint32_t aq[4], bk[4], br0[4], br1[4];
            ldsm4(aq, sb + OFFB_Q + (lrow * QPH + coff) * 2);
            ldsm4(bk, sb + OFFB_K + (lrow * QPH + coff) * 2);
            ldsm4(br0, sb + OFFB_RK + (lrow * RPH + kc * 16 + lk8) * 2);
            ldsm4(br1, sb + OFFB_RK + ((lrow + 16) * RPH + kc * 16 + lk8) * 2);
            mma16816(accS[0], aq, bk[0], bk[2]);
            mma16816(accS[1], aq, bk[1], bk[3]);
            mma16816(accR[0], aq, br0[0], br0[2]);
            mma16816(accR[1], aq, br0[1], br0[3]);
            mma16816(accR[2], aq, br1[0], br1[2]);
            mma16816(accR[3], aq, br1[1], br1[3]);
        }
        int dr = lane >> 2;
        int dc = (lane & 3) * 2;
        float* wsb = wsf + h * 16 * WSP;
        float* wrb = wrf + h * 16 * WRP;
        #pragma unroll
        for (int s = 0; s < 2; s++) {
            int col = s * 8 + dc;
            wsb[dr * WSP + col]           = accS[s][0];
            wsb[dr * WSP + col + 1]       = accS[s][1];
            wsb[(dr + 8) * WSP + col]     = accS[s][2];
            wsb[(dr + 8) * WSP + col + 1] = accS[s][3];
        }
        #pragma unroll
        for (int s = 0; s < 4; s++) {
            int col = s * 8 + dc;
            wrb[dr * WRP + col]           = accR[s][0];
            wrb[dr * WRP + col + 1]       = accR[s][1];
            wrb[(dr + 8) * WRP + col]     = accR[s][2];
            wrb[(dr + 8) * WRP + col + 1] = accR[s][3];
        }
    }
    __syncthreads();

    // ---- softmax + W/W' generation ----
    if (tid < 128) {
        int h = tid >> 4, i = tid & 15;
        const float* wsb = wsf + h * 16 * WSP + i * WSP;
        const float* wrb = wrf + h * 16 * WRP;
        float s[16];
        float mx = -1e30f;
        #pragma unroll
        for (int j = 0; j < 16; j++) {
            s[j] = 0.125f * wsb[j] + 0.35355339059327373f * wrb[j * WRP + (i - j + 15)];
            mx = fmaxf(mx, s[j]);
        }
        float sum = 0.f;
        #pragma unroll
        for (int j = 0; j < 16; j++) { s[j] = __expf(s[j] - mx); sum += s[j]; }
        float inv = 1.f / sum;
        __half* w2b = w2h + (h * 16 + i) * W2P;
        #pragma unroll
        for (int q4 = 0; q4 < 4; q4++) *(uint4*)(w2b + q4 * 8) = make_uint4(0, 0, 0, 0);
        __half* wb = wh + (h * 16 + i) * WP;
        #pragma unroll
        for (int j = 0; j < 16; j++) {
            float w = s[j] * inv;
            __half hw_ = __float2half(w);
            wb[j] = hw_;
            w2b[j - i + 15] = hw_;
        }
    }
    __syncthreads();

    // ---- output phase: O = W*V + W'*RV ----
    {
        int h = wid;
        int lrow = lane & 15;
        int lk8  = (lane >> 4) * 8;
        float accO[8][4];
        #pragma unroll
        for (int i = 0; i < 8; i++)
            #pragma unroll
            for (int j = 0; j < 4; j++) accO[i][j] = 0.f;

        uint32_t aw[4], aw2a[4], aw2b[4];
        ldsm4(aw,   sb + OFFB_W  + (h * 16 * WP  + lrow * WP  + lk8) * 2);
        ldsm4(aw2a, sb + OFFB_W2 + (h * 16 * W2P + lrow * W2P + lk8) * 2);
        ldsm4(aw2b, sb + OFFB_W2 + (h * 16 * W2P + lrow * W2P + 16 + lk8) * 2);

        #pragma unroll
        for (int nc = 0; nc < 4; nc++) {
            int coff = h * 64 + nc * 16 + lk8;
            uint32_t bv[4], brv0[4], brv1[4];
            ldsm4t(bv,   sb + OFFB_V  + (lrow * QPH + coff) * 2);
            ldsm4t(brv0, sb + OFFB_RV + (lrow * RPH + nc * 16 + lk8) * 2);
            ldsm4t(brv1, sb + OFFB_RV + ((lrow + 16) * RPH + nc * 16 + lk8) * 2);
            mma16816(accO[nc * 2 + 0], aw, bv[0], bv[1]);
            mma16816(accO[nc * 2 + 1], aw, bv[2], bv[3]);
            mma16816(accO[nc * 2 + 0], aw2a, brv0[0], brv0[1]);
            mma16816(accO[nc * 2 + 1], aw2a, brv0[2], brv0[3]);
            mma16816(accO[nc * 2 + 0], aw2b, brv1[0], brv1[1]);
            mma16816(accO[nc * 2 + 1], aw2b, brv1[2], brv1[3]);
        }

        int dr = lane >> 2;
        int dc = (lane & 3) * 2;
        #pragma unroll
        for (int nc8 = 0; nc8 < 8; nc8++) {
            int col = h * 64 + nc8 * 8 + dc;
            size_t i0 = ((size_t)(n * TT + dr)) * CC + col;
            size_t i1 = ((size_t)(n * TT + dr + 8)) * CC + col;
            *(__half2*)(g_ah + i0) =
                __halves2half2(__float2half(accO[nc8][0]), __float2half(accO[nc8][1]));
            *(__half2*)(g_ah + i1) =
                __halves2half2(__float2half(accO[nc8][2]), __float2half(accO[nc8][3]));
        }
    }
}

// ---------------- 6) transpose back + residual (fp16 pout) ----------------
__global__ __launch_bounds__(256) void resid_tr(const float* __restrict__ x,
                                                float* __restrict__ out) {
    __shared__ float tile[32][33];
    int bx  = blockIdx.x;
    int hwt = bx & 31;
    int ct  = (bx >> 5) & 15;
    int t   = (bx >> 9) & 15;
    int b   = bx >> 13;
    int tid = threadIdx.x;
    {
        int c2    = (tid & 15) * 2;
        int hw_l0 = tid >> 4;
        #pragma unroll
        for (int p = 0; p < 2; p++) {
            int hw_l = hw_l0 + p * 16;
            int hw   = hwt * 32 + hw_l;
            size_t m = ((size_t)(b * HWc + hw)) * TT + t;
            __half2 hv = *(const __half2*)(g_pout + m * CC + ct * 32 + c2);
            float2 f = __half22float2(hv);
            tile[hw_l][c2]     = f.x;
            tile[hw_l][c2 + 1] = f.y;
        }
    }
    __syncthreads();
    {
        int hw_l = tid & 31;
        int c_l0 = tid >> 5;
        int hw   = hwt * 32 + hw_l;
        #pragma unroll
        for (int p = 0; p < 4; p++) {
            int c_l = c_l0 + p * 8;
            int c   = ct * 32 + c_l;
            size_t idx = (((size_t)b * CC + c) * TT + t) * HWc + hw;
            out[idx] = x[idx] + tile[hw_l][c_l];
        }
    }
}

// ---------------- host launch ----------------
extern "C" void kernel_launch(void* const* d_in, const int* in_sizes, int n_in,
                              void* d_out, int out_size) {
    const float* x      = (const float*)d_in[0];
    const float* gamma  = (const float*)d_in[1];
    const float* beta   = (const float*)d_in[2];
    const float* w_qkv  = (const float*)d_in[3];
    const float* b_qkv  = (const float*)d_in[4];
    const float* rp_k   = (const float*)d_in[5];
    const float* rp_v   = (const float*)d_in[6];
    const float* w_proj = (const float*)d_in[7];
    const float* b_proj = (const float*)d_in[8];
    float* out = (float*)d_out;

    cudaFuncSetAttribute(hmma_gemm, cudaFuncAttributeMaxDynamicSharedMemorySize, GEMM_SMEM);
    cudaFuncSetAttribute(attn, cudaFuncAttributeMaxDynamicSharedMemorySize, ATTN_SMEM);

    __half *wqh, *wph, *nh, *ah, *qkv, *pout;
    cudaGetSymbolAddress((void**)&wqh, g_wqh);
    cudaGetSymbolAddress((void**)&wph, g_wph);
    cudaGetSymbolAddress((void**)&nh, g_nh);
    cudaGetSymbolAddress((void**)&ah, g_ah);
    cudaGetSymbolAddress((void**)&qkv, g_qkv);
    cudaGetSymbolAddress((void**)&pout, g_pout);

    // attn is launch #4 (ncu target: verify cp.async load phase)
    gn_conv<<<384, 1024>>>(x, w_qkv, w_proj);
    norm_tr<<<BB * TT * (CC / 32) * (HWc / 32), 256>>>(x, gamma, beta);
    hmma_gemm<<<dim3(C3 / 128, MM / 128), 256, GEMM_SMEM>>>(nh, wqh, b_qkv, qkv, C3);
    attn<<<NN, 256, ATTN_SMEM>>>(rp_k, rp_v);
    hmma_gemm<<<dim3(CC / 128, MM / 128), 256, GEMM_SMEM>>>(ah, wph, b_proj, pout, CC);
    resid_tr<<<BB * TT * (CC / 32) * (HWc / 32), 256>>>(x, out);
}